// round 12
// baseline (speedup 1.0000x reference)
#include <cuda_runtime.h>
#include <cuda_bf16.h>
#include <math.h>
#include <cstdint>

#define NN 50000
#define FD 128
#define NC 16
#define MAXE 800000
#define SCAN_B 512

// ---------------------------------------------------------------- scratch
__device__ float g_h[NN * FD];                // GEMM output (fp32), consumed by aggregate
__device__ float g_h16[NN * NC];              // last-layer GEMM output
__device__ __nv_bfloat16 g_ah[NN * FD];       // activation split hi (GEMM input)
__device__ __nv_bfloat16 g_al[NN * FD];       // activation split lo
__device__ __nv_bfloat16 g_wth[3][FD * FD];   // W^T split hi per layer [n][k]
__device__ __nv_bfloat16 g_wtl[3][FD * FD];   // W^T split lo per layer [n][k]
__device__ float g_dinv[NN];
__device__ int   g_src[MAXE];
__device__ int   g_dst[MAXE];
__device__ int   g_cnt[NN];
__device__ int   g_tmp[NN];
__device__ int   g_bsum[128];
__device__ int   g_rowptr[NN + 1];
__device__ int   g_cursor[NN];
__device__ int2  g_csr[MAXE];                 // packed {src, __float_as_int(norm)}
__device__ int   g_is64;

// ---------------------------------------------------------------- mma helpers
__device__ __forceinline__ uint32_t smem_u32(const void* p) {
    uint32_t a;
    asm("{ .reg .u64 t; cvta.to.shared.u64 t, %1; cvt.u32.u64 %0, t; }" : "=r"(a) : "l"(p));
    return a;
}
__device__ __forceinline__ void ldm_x4(uint32_t* r, uint32_t addr) {
    asm volatile("ldmatrix.sync.aligned.m8n8.x4.shared.b16 {%0,%1,%2,%3}, [%4];"
                 : "=r"(r[0]), "=r"(r[1]), "=r"(r[2]), "=r"(r[3]) : "r"(addr));
}
__device__ __forceinline__ void mma_bf16(float* c, const uint32_t* a, uint32_t b0, uint32_t b1) {
    asm volatile(
        "mma.sync.aligned.m16n8k16.row.col.f32.bf16.bf16.f32 "
        "{%0,%1,%2,%3}, {%4,%5,%6,%7}, {%8,%9}, {%0,%1,%2,%3};"
        : "+f"(c[0]), "+f"(c[1]), "+f"(c[2]), "+f"(c[3])
        : "r"(a[0]), "r"(a[1]), "r"(a[2]), "r"(a[3]), "r"(b0), "r"(b1));
}

// ---------------------------------------------------------------- fused graph prep
__global__ void k_prep0(const int* __restrict__ w, int E, int n) {
    int i = blockIdx.x * blockDim.x + threadIdx.x;
    if (i < n) g_cnt[i] = 0;
    if (blockIdx.x == 0) {
        __shared__ int any;
        if (threadIdx.x == 0) any = 0;
        __syncthreads();
        int m = E < 2048 ? E : 2048;
        for (int j = threadIdx.x; j < m; j += blockDim.x)
            if (w[2 * j + 1] != 0) any = 1;
        __syncthreads();
        if (threadIdx.x == 0) g_is64 = (any ? 0 : 1);
    }
}
__global__ void k_convert(const int* __restrict__ w, int E) {
    int e = blockIdx.x * blockDim.x + threadIdx.x;
    if (e >= E) return;
    int s, d;
    if (g_is64) { s = w[2 * e]; d = w[2 * E + 2 * e]; }
    else        { s = w[e];     d = w[E + e]; }
    g_src[e] = s; g_dst[e] = d;
    atomicAdd(&g_cnt[d], 1);
}
__global__ void k_dinv_scan1(int n) {
    __shared__ int sh[SCAN_B];
    int i = blockIdx.x * SCAN_B + threadIdx.x;
    int v = (i < n) ? g_cnt[i] : 0;
    if (i < n) g_dinv[i] = rsqrtf((float)v + 2.0f);
    sh[threadIdx.x] = v;
    __syncthreads();
    for (int off = 1; off < SCAN_B; off <<= 1) {
        int t = (threadIdx.x >= off) ? sh[threadIdx.x - off] : 0;
        __syncthreads();
        sh[threadIdx.x] += t;
        __syncthreads();
    }
    if (i < n) g_tmp[i] = sh[threadIdx.x] - v;
    if (threadIdx.x == SCAN_B - 1) g_bsum[blockIdx.x] = sh[SCAN_B - 1];
}
__global__ void k_scan2(int nb) {
    __shared__ int sh[128];
    int v = (threadIdx.x < nb) ? g_bsum[threadIdx.x] : 0;
    sh[threadIdx.x] = v;
    __syncthreads();
    for (int off = 1; off < 128; off <<= 1) {
        int t = (threadIdx.x >= off) ? sh[threadIdx.x - off] : 0;
        __syncthreads();
        sh[threadIdx.x] += t;
        __syncthreads();
    }
    if (threadIdx.x < nb) g_bsum[threadIdx.x] = sh[threadIdx.x] - v;
}
__global__ void k_scan3(int n, int E) {
    int i = blockIdx.x * blockDim.x + threadIdx.x;
    if (i < n) {
        int r = g_tmp[i] + g_bsum[i / SCAN_B];
        g_rowptr[i] = r;
        g_cursor[i] = r;
    }
    if (i == 0) g_rowptr[n] = E;
}
__global__ void k_fill(int E) {
    int e = blockIdx.x * blockDim.x + threadIdx.x;
    if (e >= E) return;
    int s = g_src[e], d = g_dst[e];
    int pos = atomicAdd(&g_cursor[d], 1);
    g_csr[pos] = make_int2(s, __float_as_int(g_dinv[s] * g_dinv[d]));
}

// ---------------------------------------------------------------- splits
__global__ void k_splitx(const float4* __restrict__ x, int M) {
    int i = blockIdx.x * blockDim.x + threadIdx.x;
    if (i >= M * 32) return;
    float4 v = x[i];
    __nv_bfloat16 hx = __float2bfloat16(v.x), hy = __float2bfloat16(v.y);
    __nv_bfloat16 hz = __float2bfloat16(v.z), hw = __float2bfloat16(v.w);
    __nv_bfloat162 h01, h23, l01, l23;
    h01.x = hx; h01.y = hy; h23.x = hz; h23.y = hw;
    l01.x = __float2bfloat16(v.x - __bfloat162float(hx));
    l01.y = __float2bfloat16(v.y - __bfloat162float(hy));
    l23.x = __float2bfloat16(v.z - __bfloat162float(hz));
    l23.y = __float2bfloat16(v.w - __bfloat162float(hw));
    ((__nv_bfloat162*)g_ah)[i * 2] = h01; ((__nv_bfloat162*)g_ah)[i * 2 + 1] = h23;
    ((__nv_bfloat162*)g_al)[i * 2] = l01; ((__nv_bfloat162*)g_al)[i * 2 + 1] = l23;
}
__global__ void k_wsplit3(const float* __restrict__ W0, const float* __restrict__ W1,
                          const float* __restrict__ W2) {
    int i = blockIdx.x * blockDim.x + threadIdx.x;
    if (i >= 3 * FD * FD) return;
    int layer = i / (FD * FD), j = i % (FD * FD);
    const float* W = (layer == 0) ? W0 : (layer == 1) ? W1 : W2;
    int n = j >> 7, k = j & 127;
    float w = W[k * FD + n];
    __nv_bfloat16 h = __float2bfloat16(w);
    g_wth[layer][j] = h;
    g_wtl[layer][j] = __float2bfloat16(w - __bfloat162float(h));
}

// ---------------------------------------------------------------- tensor GEMM via mma.sync
// BM=64 for occupancy 2. smem: Ah(64x272) Al(64x272) Wh(128x272) Wl(128x272)
#define ROWB 272u
#define A_MATB (64u * ROWB)          // 17408
#define W_MATB (128u * ROWB)         // 34816
#define SM_AL  A_MATB
#define SM_WH  (2u * A_MATB)
#define SM_WL  (2u * A_MATB + W_MATB)
#define TG_SMEM (2u * A_MATB + 2u * W_MATB)   // 104448

__global__ __launch_bounds__(256, 2) void k_tgemm(int layer, int M)
{
    extern __shared__ char smem[];
    const int tid = threadIdx.x;
    const int wid = tid >> 5, lane = tid & 31;
    const int row0 = blockIdx.x * 64;

    const uint4* Ah4 = (const uint4*)g_ah;
    const uint4* Al4 = (const uint4*)g_al;
    const uint4* Wh4 = (const uint4*)g_wth[layer];
    const uint4* Wl4 = (const uint4*)g_wtl[layer];
    const uint4 z4 = make_uint4(0, 0, 0, 0);
    #pragma unroll 2
    for (int i = tid; i < 1024; i += 256) {          // A tiles: 64 rows x 16 chunks
        int r = i >> 4, c = i & 15;
        uint32_t off = (uint32_t)r * ROWB + (uint32_t)c * 16u;
        bool ok = (row0 + r) < M;
        *(uint4*)(smem + off)          = ok ? Ah4[(row0 + r) * 16 + c] : z4;
        *(uint4*)(smem + SM_AL + off)  = ok ? Al4[(row0 + r) * 16 + c] : z4;
    }
    #pragma unroll 4
    for (int i = tid; i < 2048; i += 256) {          // W tiles: 128 rows x 16 chunks
        int r = i >> 4, c = i & 15;
        uint32_t off = (uint32_t)r * ROWB + (uint32_t)c * 16u;
        *(uint4*)(smem + SM_WH + off) = Wh4[i];
        *(uint4*)(smem + SM_WL + off) = Wl4[i];
    }
    __syncthreads();

    const uint32_t sbase = smem_u32(smem);
    const int m0 = (wid & 1) * 32;          // warp row block (2 x 32)
    const int n0 = (wid >> 1) * 32;         // warp col block (4 x 32)
    const int l7 = lane & 7;

    uint32_t aoff0 = (uint32_t)(m0 + ((lane >> 3) & 1) * 8 + l7) * ROWB + (uint32_t)(lane >> 4) * 16u;
    uint32_t aoff1 = aoff0 + 16u * ROWB;
    uint32_t boff[2];
    #pragma unroll
    for (int j = 0; j < 2; j++)
        boff[j] = (uint32_t)(n0 + 16 * j + (lane >> 4) * 8 + l7) * ROWB + (uint32_t)((lane >> 3) & 1) * 16u;

    float c[2][4][4];
    #pragma unroll
    for (int mt = 0; mt < 2; mt++)
        #pragma unroll
        for (int nt = 0; nt < 4; nt++)
            #pragma unroll
            for (int q = 0; q < 4; q++) c[mt][nt][q] = 0.f;

    #pragma unroll
    for (int p = 0; p < 3; p++) {
        uint32_t Ab = sbase + (p == 1 ? SM_AL : 0u);
        uint32_t Wb = sbase + (p == 2 ? SM_WL : SM_WH);
        #pragma unroll
        for (int kc = 0; kc < 8; kc++) {
            uint32_t kb = (uint32_t)kc * 32u;
            uint32_t a0[4], a1[4], b[2][4];
            ldm_x4(a0, Ab + aoff0 + kb);
            ldm_x4(a1, Ab + aoff1 + kb);
            #pragma unroll
            for (int j = 0; j < 2; j++) ldm_x4(b[j], Wb + boff[j] + kb);
            #pragma unroll
            for (int nt = 0; nt < 4; nt++) {
                uint32_t b0 = (nt & 1) ? b[nt >> 1][2] : b[nt >> 1][0];
                uint32_t b1 = (nt & 1) ? b[nt >> 1][3] : b[nt >> 1][1];
                mma_bf16(c[0][nt], a0, b0, b1);
                mma_bf16(c[1][nt], a1, b0, b1);
            }
        }
    }

    // epilogue: fp32 -> g_h, float2 coalesced
    const int g = lane >> 2, tg = lane & 3;
    #pragma unroll
    for (int mt = 0; mt < 2; mt++) {
        int rbase = row0 + m0 + mt * 16 + g;
        #pragma unroll
        for (int nt = 0; nt < 4; nt++) {
            int col = n0 + nt * 8 + tg * 2;
            if (rbase < M)
                ((float2*)g_h)[(rbase * FD + col) >> 1] = make_float2(c[mt][nt][0], c[mt][nt][1]);
            if (rbase + 8 < M)
                ((float2*)g_h)[((rbase + 8) * FD + col) >> 1] = make_float2(c[mt][nt][2], c[mt][nt][3]);
        }
    }
}

// ---------------------------------------------------------------- GEMM 128x16 (last layer)
__global__ __launch_bounds__(256) void k_gemm16(const float* __restrict__ W, int M)
{
    __shared__ float Ws[FD * NC];
    __shared__ float Xs[16 * FD];
    const int tid = threadIdx.x;
    const int row0 = blockIdx.x * 16;

    #pragma unroll
    for (int i = tid; i < FD * NC / 4; i += 256)
        ((float4*)Ws)[i] = ((const float4*)W)[i];
    const __nv_bfloat162* A2h = (const __nv_bfloat162*)g_ah;
    const __nv_bfloat162* A2l = (const __nv_bfloat162*)g_al;
    #pragma unroll
    for (int i = tid; i < 16 * FD / 4; i += 256) {
        int r = i >> 5, cc = i & 31;
        int gr = row0 + r;
        float4 v = make_float4(0.f, 0.f, 0.f, 0.f);
        if (gr < M) {
            int idx = gr * 64 + cc * 2;
            __nv_bfloat162 h0 = A2h[idx], l0 = A2l[idx];
            __nv_bfloat162 h1 = A2h[idx + 1], l1 = A2l[idx + 1];
            v.x = __bfloat162float(h0.x) + __bfloat162float(l0.x);
            v.y = __bfloat162float(h0.y) + __bfloat162float(l0.y);
            v.z = __bfloat162float(h1.x) + __bfloat162float(l1.x);
            v.w = __bfloat162float(h1.y) + __bfloat162float(l1.y);
        }
        ((float4*)Xs)[i] = v;
    }
    __syncthreads();

    const int r = tid >> 4, cc = tid & 15;
    float acc = 0.f;
    #pragma unroll 8
    for (int k = 0; k < FD; k++) acc += Xs[r * FD + k] * Ws[k * NC + cc];

    int gr = row0 + r;
    if (gr < M) g_h16[gr * NC + cc] = acc;
}

// ---------------------------------------------------------------- fused aggregate (CSR)
__global__ __launch_bounds__(256) void k_agg128(const float4* __restrict__ b, int N)
{
    int warp = (blockIdx.x * blockDim.x + threadIdx.x) >> 5;
    int lane = threadIdx.x & 31;
    if (warp >= N) return;
    int beg = g_rowptr[warp], end = g_rowptr[warp + 1];
    float dv = g_dinv[warp];
    float s = 2.0f * dv * dv;
    const float4* h4 = (const float4*)g_h;

    float4 acc = h4[warp * 32 + lane];
    float4 bv = b[lane];
    acc.x = acc.x * s + bv.x; acc.y = acc.y * s + bv.y;
    acc.z = acc.z * s + bv.z; acc.w = acc.w * s + bv.w;

    int e = beg;
    for (; e + 1 < end; e += 2) {
        int2 c0 = g_csr[e], c1 = g_csr[e + 1];
        float4 v0 = h4[c0.x * 32 + lane];
        float4 v1 = h4[c1.x * 32 + lane];
        float n0 = __int_as_float(c0.y), n1 = __int_as_float(c1.y);
        acc.x += n0 * v0.x + n1 * v1.x;
        acc.y += n0 * v0.y + n1 * v1.y;
        acc.z += n0 * v0.z + n1 * v1.z;
        acc.w += n0 * v0.w + n1 * v1.w;
    }
    if (e < end) {
        int2 c0 = g_csr[e];
        float4 v0 = h4[c0.x * 32 + lane];
        float n0 = __int_as_float(c0.y);
        acc.x += n0 * v0.x; acc.y += n0 * v0.y;
        acc.z += n0 * v0.z; acc.w += n0 * v0.w;
    }

    // relu + bf16 hi/lo split for next GEMM
    float tx = fmaxf(acc.x, 0.f), ty = fmaxf(acc.y, 0.f);
    float tz = fmaxf(acc.z, 0.f), tw = fmaxf(acc.w, 0.f);
    __nv_bfloat16 hx = __float2bfloat16(tx), hy = __float2bfloat16(ty);
    __nv_bfloat16 hz = __float2bfloat16(tz), hw = __float2bfloat16(tw);
    __nv_bfloat162 h01, h23, l01, l23;
    h01.x = hx; h01.y = hy; h23.x = hz; h23.y = hw;
    l01.x = __float2bfloat16(tx - __bfloat162float(hx));
    l01.y = __float2bfloat16(ty - __bfloat162float(hy));
    l23.x = __float2bfloat16(tz - __bfloat162float(hz));
    l23.y = __float2bfloat16(tw - __bfloat162float(hw));
    int base = warp * 64 + lane * 2;
    ((__nv_bfloat162*)g_ah)[base] = h01; ((__nv_bfloat162*)g_ah)[base + 1] = h23;
    ((__nv_bfloat162*)g_al)[base] = l01; ((__nv_bfloat162*)g_al)[base + 1] = l23;
}

// last layer: fused bias + self-loop + aggregate + tanh -> out
__global__ __launch_bounds__(256) void k_agg16(const float4* __restrict__ b,
                                               float4* __restrict__ out, int N)
{
    int t = blockIdx.x * blockDim.x + threadIdx.x;
    int node = t >> 2, q = t & 3;
    if (node >= N) return;
    int beg = g_rowptr[node], end = g_rowptr[node + 1];
    float dv = g_dinv[node];
    float s = 2.0f * dv * dv;
    const float4* h4 = (const float4*)g_h16;

    float4 acc = h4[node * 4 + q];
    float4 bv = b[q];
    acc.x = acc.x * s + bv.x; acc.y = acc.y * s + bv.y;
    acc.z = acc.z * s + bv.z; acc.w = acc.w * s + bv.w;

    for (int e = beg; e < end; e++) {
        int2 cc = g_csr[e];
        float4 v = h4[cc.x * 4 + q];
        float n = __int_as_float(cc.y);
        acc.x += n * v.x; acc.y += n * v.y;
        acc.z += n * v.z; acc.w += n * v.w;
    }
    acc.x = tanhf(acc.x); acc.y = tanhf(acc.y);
    acc.z = tanhf(acc.z); acc.w = tanhf(acc.w);
    out[node * 4 + q] = acc;
}

// ---------------------------------------------------------------- launch
extern "C" void kernel_launch(void* const* d_in, const int* in_sizes, int n_in,
                              void* d_out, int out_size)
{
    const float* x  = (const float*)d_in[0];
    const int*   ew = (const int*)d_in[1];
    const float* W0 = (const float*)d_in[2];
    const float* b0 = (const float*)d_in[3];
    const float* W1 = (const float*)d_in[4];
    const float* b1 = (const float*)d_in[5];
    const float* W2 = (const float*)d_in[6];
    const float* b2 = (const float*)d_in[7];
    const float* W3 = (const float*)d_in[8];
    const float* b3 = (const float*)d_in[9];
    float* out = (float*)d_out;

    const int E = in_sizes[1] / 2;
    const int M = in_sizes[0] / FD;

    cudaFuncSetAttribute(k_tgemm, cudaFuncAttributeMaxDynamicSharedMemorySize, (int)TG_SMEM);

    // ---- graph + weight/input prep (fused) ----
    const int nb = (M + SCAN_B - 1) / SCAN_B;
    k_prep0<<<(M + 255) / 256, 256>>>(ew, E, M);
    k_convert<<<(E + 255) / 256, 256>>>(ew, E);
    k_dinv_scan1<<<nb, SCAN_B>>>(M);
    k_scan2<<<1, 128>>>(nb);
    k_scan3<<<(M + 255) / 256, 256>>>(M, E);
    k_fill<<<(E + 255) / 256, 256>>>(E);
    k_wsplit3<<<192, 256>>>(W0, W1, W2);
    k_splitx<<<(M * 32 + 255) / 256, 256>>>((const float4*)x, M);

    const int gT = (M + 63) / 64;
    const int gAgg128 = (M * 32 + 255) / 256;
    const int gAgg16  = (M * 4 + 255) / 256;

    // Layer 0
    k_tgemm<<<gT, 256, TG_SMEM>>>(0, M);
    k_agg128<<<gAgg128, 256>>>((const float4*)b0, M);
    // Layer 1
    k_tgemm<<<gT, 256, TG_SMEM>>>(1, M);
    k_agg128<<<gAgg128, 256>>>((const float4*)b1, M);
    // Layer 2
    k_tgemm<<<gT, 256, TG_SMEM>>>(2, M);
    k_agg128<<<gAgg128, 256>>>((const float4*)b2, M);
    // Layer 3 (16-wide) fused: gemm -> aggregate+bias+tanh -> out
    k_gemm16<<<(M + 15) / 16, 256>>>(W3, M);
    k_agg16<<<gAgg16, 256>>>((const float4*)b3, (float4*)out, M);
}

// round 13
// speedup vs baseline: 1.1099x; 1.1099x over previous
#include <cuda_runtime.h>
#include <cuda_bf16.h>
#include <math.h>
#include <cstdint>

#define NN 50000
#define FD 128
#define NC 16
#define MAXE 800000
#define SCAN_B 512

// ---------------------------------------------------------------- scratch
__device__ float g_h[NN * FD];                // GEMM output (fp32), consumed by aggregate
__device__ float g_h16[NN * NC];              // last-layer GEMM output
__device__ __nv_bfloat16 g_ah[NN * FD];       // activation split hi (GEMM input)
__device__ __nv_bfloat16 g_al[NN * FD];       // activation split lo
__device__ __nv_bfloat16 g_wth[3][FD * FD];   // W^T split hi per layer [n][k]
__device__ __nv_bfloat16 g_wtl[3][FD * FD];   // W^T split lo per layer [n][k]
__device__ float g_dinv[NN];
__device__ int   g_cnt[NN];
__device__ int   g_tmp[NN];
__device__ int   g_bsum[128];
__device__ int   g_rowptr[NN + 1];
__device__ int   g_cursor[NN];
__device__ int2  g_csr[MAXE];                 // packed {src, __float_as_int(norm)}
__device__ int   g_is64;

// ---------------------------------------------------------------- mma helpers
__device__ __forceinline__ uint32_t smem_u32(const void* p) {
    uint32_t a;
    asm("{ .reg .u64 t; cvta.to.shared.u64 t, %1; cvt.u32.u64 %0, t; }" : "=r"(a) : "l"(p));
    return a;
}
__device__ __forceinline__ void ldm_x4(uint32_t* r, uint32_t addr) {
    asm volatile("ldmatrix.sync.aligned.m8n8.x4.shared.b16 {%0,%1,%2,%3}, [%4];"
                 : "=r"(r[0]), "=r"(r[1]), "=r"(r[2]), "=r"(r[3]) : "r"(addr));
}
__device__ __forceinline__ void mma_bf16(float* c, const uint32_t* a, uint32_t b0, uint32_t b1) {
    asm volatile(
        "mma.sync.aligned.m16n8k16.row.col.f32.bf16.bf16.f32 "
        "{%0,%1,%2,%3}, {%4,%5,%6,%7}, {%8,%9}, {%0,%1,%2,%3};"
        : "+f"(c[0]), "+f"(c[1]), "+f"(c[2]), "+f"(c[3])
        : "r"(a[0]), "r"(a[1]), "r"(a[2]), "r"(a[3]), "r"(b0), "r"(b1));
}

// ---------------------------------------------------------------- edge decode (inline)
__device__ __forceinline__ void edge_decode(const int* __restrict__ w, int E, int e,
                                            int& s, int& d) {
    if (g_is64) { s = w[2 * e]; d = w[2 * E + 2 * e]; }
    else        { s = w[e];     d = w[E + e]; }
}

// ---------------------------------------------------------------- fused graph prep
__global__ void k_prep0(const int* __restrict__ w, int E, int n) {
    int i = blockIdx.x * blockDim.x + threadIdx.x;
    if (i < n) g_cnt[i] = 0;
    if (blockIdx.x == 0) {
        __shared__ int any;
        if (threadIdx.x == 0) any = 0;
        __syncthreads();
        int m = E < 2048 ? E : 2048;
        for (int j = threadIdx.x; j < m; j += blockDim.x)
            if (w[2 * j + 1] != 0) any = 1;
        __syncthreads();
        if (threadIdx.x == 0) g_is64 = (any ? 0 : 1);
    }
}
__global__ void k_convert(const int* __restrict__ w, int E) {
    int e = blockIdx.x * blockDim.x + threadIdx.x;
    if (e >= E) return;
    int s, d;
    edge_decode(w, E, e, s, d);
    atomicAdd(&g_cnt[d], 1);
}
__global__ void k_dinv_scan1(int n) {
    __shared__ int sh[SCAN_B];
    int i = blockIdx.x * SCAN_B + threadIdx.x;
    int v = (i < n) ? g_cnt[i] : 0;
    if (i < n) g_dinv[i] = rsqrtf((float)v + 2.0f);
    sh[threadIdx.x] = v;
    __syncthreads();
    for (int off = 1; off < SCAN_B; off <<= 1) {
        int t = (threadIdx.x >= off) ? sh[threadIdx.x - off] : 0;
        __syncthreads();
        sh[threadIdx.x] += t;
        __syncthreads();
    }
    if (i < n) g_tmp[i] = sh[threadIdx.x] - v;
    if (threadIdx.x == SCAN_B - 1) g_bsum[blockIdx.x] = sh[SCAN_B - 1];
}
__global__ void k_scan2(int nb) {
    __shared__ int sh[128];
    int v = (threadIdx.x < nb) ? g_bsum[threadIdx.x] : 0;
    sh[threadIdx.x] = v;
    __syncthreads();
    for (int off = 1; off < 128; off <<= 1) {
        int t = (threadIdx.x >= off) ? sh[threadIdx.x - off] : 0;
        __syncthreads();
        sh[threadIdx.x] += t;
        __syncthreads();
    }
    if (threadIdx.x < nb) g_bsum[threadIdx.x] = sh[threadIdx.x] - v;
}
__global__ void k_scan3(int n, int E) {
    int i = blockIdx.x * blockDim.x + threadIdx.x;
    if (i < n) {
        int r = g_tmp[i] + g_bsum[i / SCAN_B];
        g_rowptr[i] = r;
        g_cursor[i] = r;
    }
    if (i == 0) g_rowptr[n] = E;
}
__global__ void k_fill(const int* __restrict__ w, int E) {
    int e = blockIdx.x * blockDim.x + threadIdx.x;
    if (e >= E) return;
    int s, d;
    edge_decode(w, E, e, s, d);
    int pos = atomicAdd(&g_cursor[d], 1);
    g_csr[pos] = make_int2(s, __float_as_int(g_dinv[s] * g_dinv[d]));
}

// ---------------------------------------------------------------- fused W-split + x-split
// indices [0, 3*FD*FD): weight transpose+split; [3*FD*FD, +M*32): x split (float4 units)
__global__ void k_wx(const float* __restrict__ W0, const float* __restrict__ W1,
                     const float* __restrict__ W2, const float4* __restrict__ x, int M) {
    int i = blockIdx.x * blockDim.x + threadIdx.x;
    if (i < 3 * FD * FD) {
        int layer = i / (FD * FD), j = i % (FD * FD);
        const float* W = (layer == 0) ? W0 : (layer == 1) ? W1 : W2;
        int n = j >> 7, k = j & 127;
        float w = W[k * FD + n];
        __nv_bfloat16 h = __float2bfloat16(w);
        g_wth[layer][j] = h;
        g_wtl[layer][j] = __float2bfloat16(w - __bfloat162float(h));
        return;
    }
    int j = i - 3 * FD * FD;
    if (j >= M * 32) return;
    float4 v = x[j];
    __nv_bfloat16 hx = __float2bfloat16(v.x), hy = __float2bfloat16(v.y);
    __nv_bfloat16 hz = __float2bfloat16(v.z), hw = __float2bfloat16(v.w);
    __nv_bfloat162 h01, h23, l01, l23;
    h01.x = hx; h01.y = hy; h23.x = hz; h23.y = hw;
    l01.x = __float2bfloat16(v.x - __bfloat162float(hx));
    l01.y = __float2bfloat16(v.y - __bfloat162float(hy));
    l23.x = __float2bfloat16(v.z - __bfloat162float(hz));
    l23.y = __float2bfloat16(v.w - __bfloat162float(hw));
    ((__nv_bfloat162*)g_ah)[j * 2] = h01; ((__nv_bfloat162*)g_ah)[j * 2 + 1] = h23;
    ((__nv_bfloat162*)g_al)[j * 2] = l01; ((__nv_bfloat162*)g_al)[j * 2 + 1] = l23;
}

// ---------------------------------------------------------------- tensor GEMM via mma.sync
// Proven R8 config: BM=128, occ 1. smem: 4 matrices of 128 rows x 272 B
#define ROWB 272
#define MATB (128 * ROWB)          // 34816
#define TG_SMEM (4 * MATB)         // 139264

__global__ __launch_bounds__(256, 1) void k_tgemm(int layer, int M)
{
    extern __shared__ char smem[];
    const int tid = threadIdx.x;
    const int wid = tid >> 5, lane = tid & 31;
    const int row0 = blockIdx.x * 128;

    const uint4* Ah4 = (const uint4*)g_ah;
    const uint4* Al4 = (const uint4*)g_al;
    const uint4* Wh4 = (const uint4*)g_wth[layer];
    const uint4* Wl4 = (const uint4*)g_wtl[layer];
    const uint4 z4 = make_uint4(0, 0, 0, 0);
    #pragma unroll 4
    for (int i = tid; i < 2048; i += 256) {
        int r = i >> 4, c = i & 15;
        uint32_t off = (uint32_t)(r * ROWB + c * 16);
        bool ok = (row0 + r) < M;
        *(uint4*)(smem + off)            = ok ? Ah4[(row0 + r) * 16 + c] : z4;
        *(uint4*)(smem + MATB + off)     = ok ? Al4[(row0 + r) * 16 + c] : z4;
        *(uint4*)(smem + 2 * MATB + off) = Wh4[i];
        *(uint4*)(smem + 3 * MATB + off) = Wl4[i];
    }
    __syncthreads();

    const uint32_t sbase = smem_u32(smem);
    const int m0 = (wid & 3) * 32;          // warp row block (4 x 32)
    const int n0 = (wid >> 2) * 64;         // warp col block (2 x 64)
    const int l7 = lane & 7;

    uint32_t aoff0 = (uint32_t)((m0 + ((lane >> 3) & 1) * 8 + l7) * ROWB + (lane >> 4) * 16);
    uint32_t aoff1 = aoff0 + 16 * ROWB;
    uint32_t boff[4];
    #pragma unroll
    for (int j = 0; j < 4; j++)
        boff[j] = (uint32_t)((n0 + 16 * j + (lane >> 4) * 8 + l7) * ROWB + ((lane >> 3) & 1) * 16);

    float c[2][8][4];
    #pragma unroll
    for (int mt = 0; mt < 2; mt++)
        #pragma unroll
        for (int nt = 0; nt < 8; nt++)
            #pragma unroll
            for (int q = 0; q < 4; q++) c[mt][nt][q] = 0.f;

    #pragma unroll
    for (int p = 0; p < 3; p++) {
        uint32_t Ab = sbase + (p == 1 ? MATB : 0);
        uint32_t Wb = sbase + (p == 2 ? 3 * MATB : 2 * MATB);
        #pragma unroll
        for (int kc = 0; kc < 8; kc++) {
            uint32_t kb = (uint32_t)kc * 32;
            uint32_t a0[4], a1[4], b[4][4];
            ldm_x4(a0, Ab + aoff0 + kb);
            ldm_x4(a1, Ab + aoff1 + kb);
            #pragma unroll
            for (int j = 0; j < 4; j++) ldm_x4(b[j], Wb + boff[j] + kb);
            #pragma unroll
            for (int nt = 0; nt < 8; nt++) {
                uint32_t b0 = (nt & 1) ? b[nt >> 1][2] : b[nt >> 1][0];
                uint32_t b1 = (nt & 1) ? b[nt >> 1][3] : b[nt >> 1][1];
                mma_bf16(c[0][nt], a0, b0, b1);
                mma_bf16(c[1][nt], a1, b0, b1);
            }
        }
    }

    // epilogue: fp32 -> g_h, float2 coalesced
    const int g = lane >> 2, tg = lane & 3;
    #pragma unroll
    for (int mt = 0; mt < 2; mt++) {
        int rbase = row0 + m0 + mt * 16 + g;
        #pragma unroll
        for (int nt = 0; nt < 8; nt++) {
            int col = n0 + nt * 8 + tg * 2;
            if (rbase < M)
                ((float2*)g_h)[(rbase * FD + col) >> 1] = make_float2(c[mt][nt][0], c[mt][nt][1]);
            if (rbase + 8 < M)
                ((float2*)g_h)[((rbase + 8) * FD + col) >> 1] = make_float2(c[mt][nt][2], c[mt][nt][3]);
        }
    }
}

// ---------------------------------------------------------------- GEMM 128x16 (last layer)
__global__ __launch_bounds__(256) void k_gemm16(const float* __restrict__ W, int M)
{
    __shared__ float Ws[FD * NC];
    __shared__ float Xs[16 * FD];
    const int tid = threadIdx.x;
    const int row0 = blockIdx.x * 16;

    #pragma unroll
    for (int i = tid; i < FD * NC / 4; i += 256)
        ((float4*)Ws)[i] = ((const float4*)W)[i];
    const __nv_bfloat162* A2h = (const __nv_bfloat162*)g_ah;
    const __nv_bfloat162* A2l = (const __nv_bfloat162*)g_al;
    #pragma unroll
    for (int i = tid; i < 16 * FD / 4; i += 256) {
        int r = i >> 5, cc = i & 31;
        int gr = row0 + r;
        float4 v = make_float4(0.f, 0.f, 0.f, 0.f);
        if (gr < M) {
            int idx = gr * 64 + cc * 2;
            __nv_bfloat162 h0 = A2h[idx], l0 = A2l[idx];
            __nv_bfloat162 h1 = A2h[idx + 1], l1 = A2l[idx + 1];
            v.x = __bfloat162float(h0.x) + __bfloat162float(l0.x);
            v.y = __bfloat162float(h0.y) + __bfloat162float(l0.y);
            v.z = __bfloat162float(h1.x) + __bfloat162float(l1.x);
            v.w = __bfloat162float(h1.y) + __bfloat162float(l1.y);
        }
        ((float4*)Xs)[i] = v;
    }
    __syncthreads();

    const int r = tid >> 4, cc = tid & 15;
    float acc = 0.f;
    #pragma unroll 8
    for (int k = 0; k < FD; k++) acc += Xs[r * FD + k] * Ws[k * NC + cc];

    int gr = row0 + r;
    if (gr < M) g_h16[gr * NC + cc] = acc;
}

// ---------------------------------------------------------------- fused aggregate (CSR)
__global__ __launch_bounds__(256) void k_agg128(const float4* __restrict__ b, int N)
{
    int warp = (blockIdx.x * blockDim.x + threadIdx.x) >> 5;
    int lane = threadIdx.x & 31;
    if (warp >= N) return;
    int beg = g_rowptr[warp], end = g_rowptr[warp + 1];
    float dv = g_dinv[warp];
    float s = 2.0f * dv * dv;
    const float4* h4 = (const float4*)g_h;

    float4 acc = h4[warp * 32 + lane];
    float4 bv = b[lane];
    acc.x = acc.x * s + bv.x; acc.y = acc.y * s + bv.y;
    acc.z = acc.z * s + bv.z; acc.w = acc.w * s + bv.w;

    int e = beg;
    for (; e + 1 < end; e += 2) {
        int2 c0 = g_csr[e], c1 = g_csr[e + 1];
        float4 v0 = h4[c0.x * 32 + lane];
        float4 v1 = h4[c1.x * 32 + lane];
        float n0 = __int_as_float(c0.y), n1 = __int_as_float(c1.y);
        acc.x += n0 * v0.x + n1 * v1.x;
        acc.y += n0 * v0.y + n1 * v1.y;
        acc.z += n0 * v0.z + n1 * v1.z;
        acc.w += n0 * v0.w + n1 * v1.w;
    }
    if (e < end) {
        int2 c0 = g_csr[e];
        float4 v0 = h4[c0.x * 32 + lane];
        float n0 = __int_as_float(c0.y);
        acc.x += n0 * v0.x; acc.y += n0 * v0.y;
        acc.z += n0 * v0.z; acc.w += n0 * v0.w;
    }

    // relu + bf16 hi/lo split for next GEMM
    float tx = fmaxf(acc.x, 0.f), ty = fmaxf(acc.y, 0.f);
    float tz = fmaxf(acc.z, 0.f), tw = fmaxf(acc.w, 0.f);
    __nv_bfloat16 hx = __float2bfloat16(tx), hy = __float2bfloat16(ty);
    __nv_bfloat16 hz = __float2bfloat16(tz), hw = __float2bfloat16(tw);
    __nv_bfloat162 h01, h23, l01, l23;
    h01.x = hx; h01.y = hy; h23.x = hz; h23.y = hw;
    l01.x = __float2bfloat16(tx - __bfloat162float(hx));
    l01.y = __float2bfloat16(ty - __bfloat162float(hy));
    l23.x = __float2bfloat16(tz - __bfloat162float(hz));
    l23.y = __float2bfloat16(tw - __bfloat162float(hw));
    int base = warp * 64 + lane * 2;
    ((__nv_bfloat162*)g_ah)[base] = h01; ((__nv_bfloat162*)g_ah)[base + 1] = h23;
    ((__nv_bfloat162*)g_al)[base] = l01; ((__nv_bfloat162*)g_al)[base + 1] = l23;
}

// last layer: fused bias + self-loop + aggregate + tanh -> out
__global__ __launch_bounds__(256) void k_agg16(const float4* __restrict__ b,
                                               float4* __restrict__ out, int N)
{
    int t = blockIdx.x * blockDim.x + threadIdx.x;
    int node = t >> 2, q = t & 3;
    if (node >= N) return;
    int beg = g_rowptr[node], end = g_rowptr[node + 1];
    float dv = g_dinv[node];
    float s = 2.0f * dv * dv;
    const float4* h4 = (const float4*)g_h16;

    float4 acc = h4[node * 4 + q];
    float4 bv = b[q];
    acc.x = acc.x * s + bv.x; acc.y = acc.y * s + bv.y;
    acc.z = acc.z * s + bv.z; acc.w = acc.w * s + bv.w;

    for (int e = beg; e < end; e++) {
        int2 cc = g_csr[e];
        float4 v = h4[cc.x * 4 + q];
        float n = __int_as_float(cc.y);
        acc.x += n * v.x; acc.y += n * v.y;
        acc.z += n * v.z; acc.w += n * v.w;
    }
    acc.x = tanhf(acc.x); acc.y = tanhf(acc.y);
    acc.z = tanhf(acc.z); acc.w = tanhf(acc.w);
    out[node * 4 + q] = acc;
}

// ---------------------------------------------------------------- launch
extern "C" void kernel_launch(void* const* d_in, const int* in_sizes, int n_in,
                              void* d_out, int out_size)
{
    const float* x  = (const float*)d_in[0];
    const int*   ew = (const int*)d_in[1];
    const float* W0 = (const float*)d_in[2];
    const float* b0 = (const float*)d_in[3];
    const float* W1 = (const float*)d_in[4];
    const float* b1 = (const float*)d_in[5];
    const float* W2 = (const float*)d_in[6];
    const float* b2 = (const float*)d_in[7];
    const float* W3 = (const float*)d_in[8];
    const float* b3 = (const float*)d_in[9];
    float* out = (float*)d_out;

    const int E = in_sizes[1] / 2;
    const int M = in_sizes[0] / FD;

    cudaFuncSetAttribute(k_tgemm, cudaFuncAttributeMaxDynamicSharedMemorySize, TG_SMEM);

    // ---- graph + weight/input prep (fused; no src/dst intermediates) ----
    const int nb = (M + SCAN_B - 1) / SCAN_B;
    k_prep0<<<(M + 255) / 256, 256>>>(ew, E, M);
    k_convert<<<(E + 255) / 256, 256>>>(ew, E);
    k_dinv_scan1<<<nb, SCAN_B>>>(M);
    k_scan2<<<1, 128>>>(nb);
    k_scan3<<<(M + 255) / 256, 256>>>(M, E);
    k_fill<<<(E + 255) / 256, 256>>>(ew, E);
    k_wx<<<(3 * FD * FD + M * 32 + 255) / 256, 256>>>(W0, W1, W2, (const float4*)x, M);

    const int gT = (M + 127) / 128;
    const int gAgg128 = (M * 32 + 255) / 256;
    const int gAgg16  = (M * 4 + 255) / 256;

    // Layer 0
    k_tgemm<<<gT, 256, TG_SMEM>>>(0, M);
    k_agg128<<<gAgg128, 256>>>((const float4*)b0, M);
    // Layer 1
    k_tgemm<<<gT, 256, TG_SMEM>>>(1, M);
    k_agg128<<<gAgg128, 256>>>((const float4*)b1, M);
    // Layer 2
    k_tgemm<<<gT, 256, TG_SMEM>>>(2, M);
    k_agg128<<<gAgg128, 256>>>((const float4*)b2, M);
    // Layer 3 (16-wide) fused: gemm -> aggregate+bias+tanh -> out
    k_gemm16<<<(M + 15) / 16, 256>>>(W3, M);
    k_agg16<<<gAgg16, 256>>>((const float4*)b3, (float4*)out, M);
}

// round 15
// speedup vs baseline: 1.1385x; 1.0258x over previous
#include <cuda_runtime.h>
#include <cuda_bf16.h>
#include <math.h>
#include <cstdint>

#define NN 50000
#define FD 128
#define NC 16
#define MAXE 800000
#define SCAN_B 512

// ---------------------------------------------------------------- scratch
__device__ float g_h[NN * FD];                // GEMM output (fp32), consumed by aggregate
__device__ float g_h16[NN * NC];              // last-layer GEMM output
__device__ __nv_bfloat16 g_ah[NN * FD];       // activation split hi (GEMM input)
__device__ __nv_bfloat16 g_al[NN * FD];       // activation split lo
__device__ __nv_bfloat16 g_wth[3][FD * FD];   // W^T split hi per layer [n][k]
__device__ __nv_bfloat16 g_wtl[3][FD * FD];   // W^T split lo per layer [n][k]
__device__ float g_dinv[NN];
__device__ int   g_cnt[NN];
__device__ int   g_tmp[NN];
__device__ int   g_bsum[128];
__device__ int   g_rowptr[NN + 1];
__device__ int   g_cursor[NN];
__device__ int2  g_csr[MAXE];                 // packed {src, __float_as_int(norm)}
__device__ int   g_is64;

// ---------------------------------------------------------------- mma helpers
__device__ __forceinline__ uint32_t smem_u32(const void* p) {
    uint32_t a;
    asm("{ .reg .u64 t; cvta.to.shared.u64 t, %1; cvt.u32.u64 %0, t; }" : "=r"(a) : "l"(p));
    return a;
}
__device__ __forceinline__ void ldm_x4(uint32_t* r, uint32_t addr) {
    asm volatile("ldmatrix.sync.aligned.m8n8.x4.shared.b16 {%0,%1,%2,%3}, [%4];"
                 : "=r"(r[0]), "=r"(r[1]), "=r"(r[2]), "=r"(r[3]) : "r"(addr));
}
__device__ __forceinline__ void mma_bf16(float* c, const uint32_t* a, uint32_t b0, uint32_t b1) {
    asm volatile(
        "mma.sync.aligned.m16n8k16.row.col.f32.bf16.bf16.f32 "
        "{%0,%1,%2,%3}, {%4,%5,%6,%7}, {%8,%9}, {%0,%1,%2,%3};"
        : "+f"(c[0]), "+f"(c[1]), "+f"(c[2]), "+f"(c[3])
        : "r"(a[0]), "r"(a[1]), "r"(a[2]), "r"(a[3]), "r"(b0), "r"(b1));
}

// ---------------------------------------------------------------- edge decode (inline)
__device__ __forceinline__ void edge_decode(const int* __restrict__ w, int E, int e,
                                            int& s, int& d) {
    if (g_is64) { s = w[2 * e]; d = w[2 * E + 2 * e]; }
    else        { s = w[e];     d = w[E + e]; }
}

// ---------------------------------------------------------------- fused graph prep
__global__ void k_prep0(const int* __restrict__ w, int E, int n) {
    int i = blockIdx.x * blockDim.x + threadIdx.x;
    if (i < n) g_cnt[i] = 0;
    if (blockIdx.x == 0) {
        __shared__ int any;
        if (threadIdx.x == 0) any = 0;
        __syncthreads();
        int m = E < 2048 ? E : 2048;
        for (int j = threadIdx.x; j < m; j += blockDim.x)
            if (w[2 * j + 1] != 0) any = 1;
        __syncthreads();
        if (threadIdx.x == 0) g_is64 = (any ? 0 : 1);
    }
}
__global__ void k_convert(const int* __restrict__ w, int E) {
    int e = blockIdx.x * blockDim.x + threadIdx.x;
    if (e >= E) return;
    int s, d;
    edge_decode(w, E, e, s, d);
    atomicAdd(&g_cnt[d], 1);
}
__global__ void k_dinv_scan1(int n) {
    __shared__ int sh[SCAN_B];
    int i = blockIdx.x * SCAN_B + threadIdx.x;
    int v = (i < n) ? g_cnt[i] : 0;
    if (i < n) g_dinv[i] = rsqrtf((float)v + 2.0f);
    sh[threadIdx.x] = v;
    __syncthreads();
    for (int off = 1; off < SCAN_B; off <<= 1) {
        int t = (threadIdx.x >= off) ? sh[threadIdx.x - off] : 0;
        __syncthreads();
        sh[threadIdx.x] += t;
        __syncthreads();
    }
    if (i < n) g_tmp[i] = sh[threadIdx.x] - v;
    if (threadIdx.x == SCAN_B - 1) g_bsum[blockIdx.x] = sh[SCAN_B - 1];
}
__global__ void k_scan2(int nb) {
    __shared__ int sh[128];
    int v = (threadIdx.x < nb) ? g_bsum[threadIdx.x] : 0;
    sh[threadIdx.x] = v;
    __syncthreads();
    for (int off = 1; off < 128; off <<= 1) {
        int t = (threadIdx.x >= off) ? sh[threadIdx.x - off] : 0;
        __syncthreads();
        sh[threadIdx.x] += t;
        __syncthreads();
    }
    if (threadIdx.x < nb) g_bsum[threadIdx.x] = sh[threadIdx.x] - v;
}
__global__ void k_scan3(int n, int E) {
    int i = blockIdx.x * blockDim.x + threadIdx.x;
    if (i < n) {
        int r = g_tmp[i] + g_bsum[i / SCAN_B];
        g_rowptr[i] = r;
        g_cursor[i] = r;
    }
    if (i == 0) g_rowptr[n] = E;
}
__global__ void k_fill(const int* __restrict__ w, int E) {
    int e = blockIdx.x * blockDim.x + threadIdx.x;
    if (e >= E) return;
    int s, d;
    edge_decode(w, E, e, s, d);
    int pos = atomicAdd(&g_cursor[d], 1);
    g_csr[pos] = make_int2(s, __float_as_int(g_dinv[s] * g_dinv[d]));
}

// ---------------------------------------------------------------- fused W-split + x-split
__global__ void k_wx(const float* __restrict__ W0, const float* __restrict__ W1,
                     const float* __restrict__ W2, const float4* __restrict__ x, int M) {
    int i = blockIdx.x * blockDim.x + threadIdx.x;
    if (i < 3 * FD * FD) {
        int layer = i / (FD * FD), j = i % (FD * FD);
        const float* W = (layer == 0) ? W0 : (layer == 1) ? W1 : W2;
        int n = j >> 7, k = j & 127;
        float w = W[k * FD + n];
        __nv_bfloat16 h = __float2bfloat16(w);
        g_wth[layer][j] = h;
        g_wtl[layer][j] = __float2bfloat16(w - __bfloat162float(h));
        return;
    }
    int j = i - 3 * FD * FD;
    if (j >= M * 32) return;
    float4 v = x[j];
    __nv_bfloat16 hx = __float2bfloat16(v.x), hy = __float2bfloat16(v.y);
    __nv_bfloat16 hz = __float2bfloat16(v.z), hw = __float2bfloat16(v.w);
    __nv_bfloat162 h01, h23, l01, l23;
    h01.x = hx; h01.y = hy; h23.x = hz; h23.y = hw;
    l01.x = __float2bfloat16(v.x - __bfloat162float(hx));
    l01.y = __float2bfloat16(v.y - __bfloat162float(hy));
    l23.x = __float2bfloat16(v.z - __bfloat162float(hz));
    l23.y = __float2bfloat16(v.w - __bfloat162float(hw));
    ((__nv_bfloat162*)g_ah)[j * 2] = h01; ((__nv_bfloat162*)g_ah)[j * 2 + 1] = h23;
    ((__nv_bfloat162*)g_al)[j * 2] = l01; ((__nv_bfloat162*)g_al)[j * 2 + 1] = l23;
}

// ---------------------------------------------------------------- tensor GEMM via mma.sync
// BM=128, 3 smem slots (102KB) -> occupancy 2.
// S0=Ah, S1=Wh, S2=Al then Wl. Phase1: AhWh + AlWh (shared B frags). Phase2: AhWl.
#define ROWB 272
#define MATB (128 * ROWB)          // 34816
#define TG_SMEM (3 * MATB)         // 104448

__global__ __launch_bounds__(256, 2) void k_tgemm(int layer, int M)
{
    extern __shared__ char smem[];
    const int tid = threadIdx.x;
    const int wid = tid >> 5, lane = tid & 31;
    const int row0 = blockIdx.x * 128;

    const uint4* Ah4 = (const uint4*)g_ah;
    const uint4* Al4 = (const uint4*)g_al;
    const uint4* Wh4 = (const uint4*)g_wth[layer];
    const uint4* Wl4 = (const uint4*)g_wtl[layer];
    const uint4 z4 = make_uint4(0, 0, 0, 0);
    #pragma unroll 4
    for (int i = tid; i < 2048; i += 256) {
        int r = i >> 4, c = i & 15;
        uint32_t off = (uint32_t)(r * ROWB + c * 16);
        bool ok = (row0 + r) < M;
        *(uint4*)(smem + off)            = ok ? Ah4[(row0 + r) * 16 + c] : z4;
        *(uint4*)(smem + MATB + off)     = Wh4[i];
        *(uint4*)(smem + 2 * MATB + off) = ok ? Al4[(row0 + r) * 16 + c] : z4;
    }
    __syncthreads();

    const uint32_t sbase = smem_u32(smem);
    const int m0 = (wid & 3) * 32;          // warp row block (4 x 32)
    const int n0 = (wid >> 2) * 64;         // warp col block (2 x 64)
    const int l7 = lane & 7;

    uint32_t aoff0 = (uint32_t)((m0 + ((lane >> 3) & 1) * 8 + l7) * ROWB + (lane >> 4) * 16);
    uint32_t aoff1 = aoff0 + 16 * ROWB;
    uint32_t boff[4];
    #pragma unroll
    for (int j = 0; j < 4; j++)
        boff[j] = (uint32_t)((n0 + 16 * j + (lane >> 4) * 8 + l7) * ROWB + ((lane >> 3) & 1) * 16);

    float c[2][8][4];
    #pragma unroll
    for (int mt = 0; mt < 2; mt++)
        #pragma unroll
        for (int nt = 0; nt < 8; nt++)
            #pragma unroll
            for (int q = 0; q < 4; q++) c[mt][nt][q] = 0.f;

    // Phase 1: AhWh + AlWh (B fragments shared across both products)
    #pragma unroll
    for (int kc = 0; kc < 8; kc++) {
        uint32_t kb = (uint32_t)kc * 32;
        uint32_t a0h[4], a1h[4], a0l[4], a1l[4], b[4][4];
        ldm_x4(a0h, sbase + aoff0 + kb);
        ldm_x4(a1h, sbase + aoff1 + kb);
        ldm_x4(a0l, sbase + 2 * MATB + aoff0 + kb);
        ldm_x4(a1l, sbase + 2 * MATB + aoff1 + kb);
        #pragma unroll
        for (int j = 0; j < 4; j++) ldm_x4(b[j], sbase + MATB + boff[j] + kb);
        #pragma unroll
        for (int nt = 0; nt < 8; nt++) {
            uint32_t b0 = (nt & 1) ? b[nt >> 1][2] : b[nt >> 1][0];
            uint32_t b1 = (nt & 1) ? b[nt >> 1][3] : b[nt >> 1][1];
            mma_bf16(c[0][nt], a0h, b0, b1);
            mma_bf16(c[1][nt], a1h, b0, b1);
            mma_bf16(c[0][nt], a0l, b0, b1);
            mma_bf16(c[1][nt], a1l, b0, b1);
        }
    }

    // Swap: overwrite Al slot with Wl
    __syncthreads();
    #pragma unroll 4
    for (int i = tid; i < 2048; i += 256) {
        int r = i >> 4, c2 = i & 15;
        uint32_t off = (uint32_t)(r * ROWB + c2 * 16);
        *(uint4*)(smem + 2 * MATB + off) = Wl4[i];
    }
    __syncthreads();

    // Phase 2: AhWl
    #pragma unroll
    for (int kc = 0; kc < 8; kc++) {
        uint32_t kb = (uint32_t)kc * 32;
        uint32_t a0h[4], a1h[4], b[4][4];
        ldm_x4(a0h, sbase + aoff0 + kb);
        ldm_x4(a1h, sbase + aoff1 + kb);
        #pragma unroll
        for (int j = 0; j < 4; j++) ldm_x4(b[j], sbase + 2 * MATB + boff[j] + kb);
        #pragma unroll
        for (int nt = 0; nt < 8; nt++) {
            uint32_t b0 = (nt & 1) ? b[nt >> 1][2] : b[nt >> 1][0];
            uint32_t b1 = (nt & 1) ? b[nt >> 1][3] : b[nt >> 1][1];
            mma_bf16(c[0][nt], a0h, b0, b1);
            mma_bf16(c[1][nt], a1h, b0, b1);
        }
    }

    // epilogue: fp32 -> g_h, float2 coalesced
    const int g = lane >> 2, tg = lane & 3;
    #pragma unroll
    for (int mt = 0; mt < 2; mt++) {
        int rbase = row0 + m0 + mt * 16 + g;
        #pragma unroll
        for (int nt = 0; nt < 8; nt++) {
            int col = n0 + nt * 8 + tg * 2;
            if (rbase < M)
                ((float2*)g_h)[(rbase * FD + col) >> 1] = make_float2(c[mt][nt][0], c[mt][nt][1]);
            if (rbase + 8 < M)
                ((float2*)g_h)[((rbase + 8) * FD + col) >> 1] = make_float2(c[mt][nt][2], c[mt][nt][3]);
        }
    }
}

// ---------------------------------------------------------------- GEMM 128x16 (last layer)
__global__ __launch_bounds__(256) void k_gemm16(const float* __restrict__ W, int M)
{
    __shared__ float Ws[FD * NC];
    __shared__ float Xs[16 * FD];
    const int tid = threadIdx.x;
    const int row0 = blockIdx.x * 16;

    #pragma unroll
    for (int i = tid; i < FD * NC / 4; i += 256)
        ((float4*)Ws)[i] = ((const float4*)W)[i];
    const __nv_bfloat162* A2h = (const __nv_bfloat162*)g_ah;
    const __nv_bfloat162* A2l = (const __nv_bfloat162*)g_al;
    #pragma unroll
    for (int i = tid; i < 16 * FD / 4; i += 256) {
        int r = i >> 5, cc = i & 31;
        int gr = row0 + r;
        float4 v = make_float4(0.f, 0.f, 0.f, 0.f);
        if (gr < M) {
            int idx = gr * 64 + cc * 2;
            __nv_bfloat162 h0 = A2h[idx], l0 = A2l[idx];
            __nv_bfloat162 h1 = A2h[idx + 1], l1 = A2l[idx + 1];
            v.x = __bfloat162float(h0.x) + __bfloat162float(l0.x);
            v.y = __bfloat162float(h0.y) + __bfloat162float(l0.y);
            v.z = __bfloat162float(h1.x) + __bfloat162float(l1.x);
            v.w = __bfloat162float(h1.y) + __bfloat162float(l1.y);
        }
        ((float4*)Xs)[i] = v;
    }
    __syncthreads();

    const int r = tid >> 4, cc = tid & 15;
    float acc = 0.f;
    #pragma unroll 8
    for (int k = 0; k < FD; k++) acc += Xs[r * FD + k] * Ws[k * NC + cc];

    int gr = row0 + r;
    if (gr < M) g_h16[gr * NC + cc] = acc;
}

// ---------------------------------------------------------------- fused aggregate (CSR)
__global__ __launch_bounds__(256) void k_agg128(const float4* __restrict__ b, int N)
{
    int warp = (blockIdx.x * blockDim.x + threadIdx.x) >> 5;
    int lane = threadIdx.x & 31;
    if (warp >= N) return;
    int beg = g_rowptr[warp], end = g_rowptr[warp + 1];
    float dv = g_dinv[warp];
    float s = 2.0f * dv * dv;
    const float4* h4 = (const float4*)g_h;

    float4 acc = h4[warp * 32 + lane];
    float4 bv = b[lane];
    acc.x = acc.x * s + bv.x; acc.y = acc.y * s + bv.y;
    acc.z = acc.z * s + bv.z; acc.w = acc.w * s + bv.w;

    int e = beg;
    for (; e + 1 < end; e += 2) {
        int2 c0 = g_csr[e], c1 = g_csr[e + 1];
        float4 v0 = h4[c0.x * 32 + lane];
        float4 v1 = h4[c1.x * 32 + lane];
        float n0 = __int_as_float(c0.y), n1 = __int_as_float(c1.y);
        acc.x += n0 * v0.x + n1 * v1.x;
        acc.y += n0 * v0.y + n1 * v1.y;
        acc.z += n0 * v0.z + n1 * v1.z;
        acc.w += n0 * v0.w + n1 * v1.w;
    }
    if (e < end) {
        int2 c0 = g_csr[e];
        float4 v0 = h4[c0.x * 32 + lane];
        float n0 = __int_as_float(c0.y);
        acc.x += n0 * v0.x; acc.y += n0 * v0.y;
        acc.z += n0 * v0.z; acc.w += n0 * v0.w;
    }

    // relu + bf16 hi/lo split for next GEMM
    float tx = fmaxf(acc.x, 0.f), ty = fmaxf(acc.y, 0.f);
    float tz = fmaxf(acc.z, 0.f), tw = fmaxf(acc.w, 0.f);
    __nv_bfloat16 hx = __float2bfloat16(tx), hy = __float2bfloat16(ty);
    __nv_bfloat16 hz = __float2bfloat16(tz), hw = __float2bfloat16(tw);
    __nv_bfloat162 h01, h23, l01, l23;
    h01.x = hx; h01.y = hy; h23.x = hz; h23.y = hw;
    l01.x = __float2bfloat16(tx - __bfloat162float(hx));
    l01.y = __float2bfloat16(ty - __bfloat162float(hy));
    l23.x = __float2bfloat16(tz - __bfloat162float(hz));
    l23.y = __float2bfloat16(tw - __bfloat162float(hw));
    int base = warp * 64 + lane * 2;
    ((__nv_bfloat162*)g_ah)[base] = h01; ((__nv_bfloat162*)g_ah)[base + 1] = h23;
    ((__nv_bfloat162*)g_al)[base] = l01; ((__nv_bfloat162*)g_al)[base + 1] = l23;
}

// last layer: fused bias + self-loop + aggregate + tanh -> out
__global__ __launch_bounds__(256) void k_agg16(const float4* __restrict__ b,
                                               float4* __restrict__ out, int N)
{
    int t = blockIdx.x * blockDim.x + threadIdx.x;
    int node = t >> 2, q = t & 3;
    if (node >= N) return;
    int beg = g_rowptr[node], end = g_rowptr[node + 1];
    float dv = g_dinv[node];
    float s = 2.0f * dv * dv;
    const float4* h4 = (const float4*)g_h16;

    float4 acc = h4[node * 4 + q];
    float4 bv = b[q];
    acc.x = acc.x * s + bv.x; acc.y = acc.y * s + bv.y;
    acc.z = acc.z * s + bv.z; acc.w = acc.w * s + bv.w;

    for (int e = beg; e < end; e++) {
        int2 cc = g_csr[e];
        float4 v = h4[cc.x * 4 + q];
        float n = __int_as_float(cc.y);
        acc.x += n * v.x; acc.y += n * v.y;
        acc.z += n * v.z; acc.w += n * v.w;
    }
    acc.x = tanhf(acc.x); acc.y = tanhf(acc.y);
    acc.z = tanhf(acc.z); acc.w = tanhf(acc.w);
    out[node * 4 + q] = acc;
}

// ---------------------------------------------------------------- launch
extern "C" void kernel_launch(void* const* d_in, const int* in_sizes, int n_in,
                              void* d_out, int out_size)
{
    const float* x  = (const float*)d_in[0];
    const int*   ew = (const int*)d_in[1];
    const float* W0 = (const float*)d_in[2];
    const float* b0 = (const float*)d_in[3];
    const float* W1 = (const float*)d_in[4];
    const float* b1 = (const float*)d_in[5];
    const float* W2 = (const float*)d_in[6];
    const float* b2 = (const float*)d_in[7];
    const float* W3 = (const float*)d_in[8];
    const float* b3 = (const float*)d_in[9];
    float* out = (float*)d_out;

    const int E = in_sizes[1] / 2;
    const int M = in_sizes[0] / FD;

    cudaFuncSetAttribute(k_tgemm, cudaFuncAttributeMaxDynamicSharedMemorySize, TG_SMEM);

    // ---- graph + weight/input prep (fused; no src/dst intermediates) ----
    const int nb = (M + SCAN_B - 1) / SCAN_B;
    k_prep0<<<(M + 255) / 256, 256>>>(ew, E, M);
    k_convert<<<(E + 255) / 256, 256>>>(ew, E);
    k_dinv_scan1<<<nb, SCAN_B>>>(M);
    k_scan2<<<1, 128>>>(nb);
    k_scan3<<<(M + 255) / 256, 256>>>(M, E);
    k_fill<<<(E + 255) / 256, 256>>>(ew, E);
    k_wx<<<(3 * FD * FD + M * 32 + 255) / 256, 256>>>(W0, W1, W2, (const float4*)x, M);

    const int gT = (M + 127) / 128;
    const int gAgg128 = (M * 32 + 255) / 256;
    const int gAgg16  = (M * 4 + 255) / 256;

    // Layer 0
    k_tgemm<<<gT, 256, TG_SMEM>>>(0, M);
    k_agg128<<<gAgg128, 256>>>((const float4*)b0, M);
    // Layer 1
    k_tgemm<<<gT, 256, TG_SMEM>>>(1, M);
    k_agg128<<<gAgg128, 256>>>((const float4*)b1, M);
    // Layer 2
    k_tgemm<<<gT, 256, TG_SMEM>>>(2, M);
    k_agg128<<<gAgg128, 256>>>((const float4*)b2, M);
    // Layer 3 (16-wide) fused: gemm -> aggregate+bias+tanh -> out
    k_gemm16<<<(M + 15) / 16, 256>>>(W3, M);
    k_agg16<<<gAgg16, 256>>>((const float4*)b3, (float4*)out, M);
}